// round 13
// baseline (speedup 1.0000x reference)
#include <cuda_runtime.h>
#include <cuda_bf16.h>
#include <math.h>
#include <cstdint>

#define NT 384
#define CZ 128
#define NH 4
#define HD 32
#define NROWS (NT*NT)   // 147456

// q pre-scale: (1/sqrt(32)) * log2(e)  -> attention uses exp2
#define QSC 0.25503540392906837f

// ---------------- scratch (device globals) ----------------
__device__ __nv_bfloat16  g_qkv_b16[(size_t)3 * NT * NH * NT * HD]; // [t][n][h][i][d]
__device__ __nv_bfloat16  g_gate_b16[(size_t)NROWS * CZ];           // sigmoid(gate), bf16
__device__ __nv_bfloat16  g_ao_b16[(size_t)NROWS * CZ];             // attention out, bf16
__device__ __nv_bfloat16  g_wqkv_b16[512 * 128];                    // [n][k]  (qkv | gate)
__device__ __nv_bfloat16  g_wout_b16[128 * 128];                    // [n][k]

// ---------------- helpers ----------------
__device__ __forceinline__ uint32_t smem_to_u32(const void* p) {
    uint32_t a;
    asm("{ .reg .u64 t; cvta.to.shared.u64 t, %1; cvt.u32.u64 %0, t; }" : "=r"(a) : "l"(p));
    return a;
}
__device__ __forceinline__ void ldsm4(uint32_t* r, uint32_t a) {
    asm volatile("ldmatrix.sync.aligned.m8n8.x4.shared.b16 {%0,%1,%2,%3}, [%4];"
        : "=r"(r[0]), "=r"(r[1]), "=r"(r[2]), "=r"(r[3]) : "r"(a));
}
__device__ __forceinline__ void mma_bf16(float* d, const uint32_t* a, const uint32_t* b) {
    asm volatile("mma.sync.aligned.m16n8k16.row.col.f32.bf16.bf16.f32 "
        "{%0,%1,%2,%3}, {%4,%5,%6,%7}, {%8,%9}, {%0,%1,%2,%3};"
        : "+f"(d[0]), "+f"(d[1]), "+f"(d[2]), "+f"(d[3])
        : "r"(a[0]), "r"(a[1]), "r"(a[2]), "r"(a[3]), "r"(b[0]), "r"(b[1]));
}
__device__ __forceinline__ uint32_t packbf(float lo, float hi) {
    __nv_bfloat162 p = __floats2bfloat162_rn(lo, hi);
    return *reinterpret_cast<uint32_t*>(&p);
}
__device__ __forceinline__ void cp16(uint32_t s, const void* g) {
    asm volatile("cp.async.cg.shared.global [%0], [%1], 16;" :: "r"(s), "l"(g));
}
#define CP_COMMIT() asm volatile("cp.async.commit_group;")
#define CP_WAIT0()  asm volatile("cp.async.wait_group 0;")
__device__ __forceinline__ float ex2(float x) {
    float y; asm("ex2.approx.ftz.f32 %0, %1;" : "=f"(y) : "f"(x)); return y;
}

// ---------------------------------------------------------------------------
// Kernel 0: convert weights to bf16, transposed to [n][k]
// ---------------------------------------------------------------------------
__global__ __launch_bounds__(256) void k_convw(const float* __restrict__ qkv_w,
                                               const float* __restrict__ gate_w,
                                               const float* __restrict__ out_w) {
    const int idx = blockIdx.x * 256 + threadIdx.x;
    if (idx < 512 * 128) {
        const int n = idx >> 7, k = idx & 127;
        const float v = (n < 384) ? qkv_w[k * 384 + n] : gate_w[k * 128 + (n - 384)];
        g_wqkv_b16[idx] = __float2bfloat16_rn(v);
    } else {
        const int j = idx - 512 * 128;   // < 16384
        const int n = j >> 7, k = j & 127;
        g_wout_b16[j] = __float2bfloat16_rn(out_w[k * 128 + n]);
    }
}

// ---------------------------------------------------------------------------
// Kernel 1: fused LN + GEMM [128 rows] x [128 -> 512 cols], pipelined, 2 CTAs/SM.
// ---------------------------------------------------------------------------
#define SPITCH 136   // bf16 elements per smem row

__global__ __launch_bounds__(256, 2) void k_gemm_ln_qkvg(const float* __restrict__ z,
                                                         const float* __restrict__ lnw,
                                                         const float* __restrict__ lnb,
                                                         const float* __restrict__ qkv_b,
                                                         const float* __restrict__ gate_b) {
    extern __shared__ __align__(16) char dyn[];
    __nv_bfloat16* sA = reinterpret_cast<__nv_bfloat16*>(dyn);
    __nv_bfloat16* sB = sA + 128 * SPITCH;
    __nv_bfloat16* sC = sB + 128 * SPITCH;
    const int tid = threadIdx.x;
    const int m0  = blockIdx.x * 128;

    const uint32_t sB_u = smem_to_u32(sB);
    const int br  = tid >> 1;           // B-copy row
    const int bh  = tid & 1;            // half-row
    const uint32_t bdst = sB_u + (uint32_t)((br * SPITCH + bh * 64) * 2);
    const __nv_bfloat16* bsrc0 = g_wqkv_b16 + (size_t)br * 128 + bh * 64;

    // ---- prefetch B tile 0 ----
    #pragma unroll
    for (int i = 0; i < 8; i++) cp16(bdst + i * 16, bsrc0 + i * 8);
    CP_COMMIT();

    // ---- LayerNorm into sA (bf16): 4 threads/row, 2 passes (32 live floats) ----
    #pragma unroll
    for (int pass = 0; pass < 2; pass++) {
        const int r = pass * 64 + (tid >> 2);
        const int qt = tid & 3;                       // quarter-row (32 floats)
        const float4* zr = reinterpret_cast<const float4*>(
            z + (size_t)(m0 + r) * 128 + qt * 32);
        float x[32];
        #pragma unroll
        for (int p = 0; p < 8; p++) {
            float4 v = zr[p];
            x[4 * p] = v.x; x[4 * p + 1] = v.y; x[4 * p + 2] = v.z; x[4 * p + 3] = v.w;
        }
        float s = 0.f, ss = 0.f;
        #pragma unroll
        for (int c = 0; c < 32; c++) { s += x[c]; ss += x[c] * x[c]; }
        s  += __shfl_xor_sync(0xffffffffu, s, 1);
        ss += __shfl_xor_sync(0xffffffffu, ss, 1);
        s  += __shfl_xor_sync(0xffffffffu, s, 2);
        ss += __shfl_xor_sync(0xffffffffu, ss, 2);
        const float mu  = s * (1.0f / 128.0f);
        const float var = ss * (1.0f / 128.0f) - mu * mu;
        const float inv = rsqrtf(var + 1e-5f);
        const float4* w4 = reinterpret_cast<const float4*>(lnw + qt * 32);
        const float4* b4 = reinterpret_cast<const float4*>(lnb + qt * 32);
        uint32_t* dst = reinterpret_cast<uint32_t*>(sA + r * SPITCH + qt * 32);
        #pragma unroll
        for (int p = 0; p < 8; p++) {
            const float4 w = w4[p], b = b4[p];
            dst[2 * p]     = packbf((x[4 * p]     - mu) * inv * w.x + b.x,
                                    (x[4 * p + 1] - mu) * inv * w.y + b.y);
            dst[2 * p + 1] = packbf((x[4 * p + 2] - mu) * inv * w.z + b.z,
                                    (x[4 * p + 3] - mu) * inv * w.w + b.w);
        }
    }
    CP_WAIT0();
    __syncthreads();

    const int lane = tid & 31, wid = tid >> 5;
    const int wm = (wid & 3) * 32;
    const int wn = (wid >> 2) * 64;
    const int quad = lane >> 2, tq = lane & 3;

    const uint32_t sA_u = smem_to_u32(sA);
    const uint32_t aaddr0 = sA_u + (uint32_t)(((wm + (lane & 15)) * SPITCH + ((lane >> 4) << 3)) * 2);
    const uint32_t aaddr1 = aaddr0 + 16 * SPITCH * 2;
    const uint32_t baddr  = sB_u + (uint32_t)(((wn + (lane & 7) + ((lane >> 4) << 3)) * SPITCH
                                               + (((lane >> 3) & 1) << 3)) * 2);

    const int rn0 = (blockIdx.x % 3) * 128;
    const int ri0 = blockIdx.x / 3;

    for (int nb = 0; nb < 4; nb++) {
        float acc[2][8][4];
        #pragma unroll
        for (int m = 0; m < 2; m++)
            #pragma unroll
            for (int n = 0; n < 8; n++)
                #pragma unroll
                for (int q = 0; q < 4; q++) acc[m][n][q] = 0.0f;

        #pragma unroll
        for (int k0 = 0; k0 < 128; k0 += 16) {
            uint32_t a0[4], a1[4];
            ldsm4(a0, aaddr0 + k0 * 2);
            ldsm4(a1, aaddr1 + k0 * 2);
            #pragma unroll
            for (int np = 0; np < 4; np++) {
                uint32_t b[4];
                ldsm4(b, baddr + (uint32_t)(np * 16 * SPITCH * 2) + k0 * 2);
                mma_bf16(acc[0][2 * np],     a0, b);
                mma_bf16(acc[0][2 * np + 1], a0, b + 2);
                mma_bf16(acc[1][2 * np],     a1, b);
                mma_bf16(acc[1][2 * np + 1], a1, b + 2);
            }
        }

        // ---- stage C tile into sC (bias / activation applied) ----
        if (nb < 3) {
            const float sc = (nb == 0) ? QSC : 1.0f;
            #pragma unroll
            for (int nsub = 0; nsub < 8; nsub++) {
                const int col = wn + nsub * 8 + tq * 2;
                const float bx = qkv_b[nb * 128 + col], by = qkv_b[nb * 128 + col + 1];
                #pragma unroll
                for (int msub = 0; msub < 2; msub++)
                    #pragma unroll
                    for (int rr = 0; rr < 2; rr++) {
                        const int row = wm + msub * 16 + quad + rr * 8;
                        *reinterpret_cast<uint32_t*>(sC + row * SPITCH + col) =
                            packbf((acc[msub][nsub][2 * rr]     + bx) * sc,
                                   (acc[msub][nsub][2 * rr + 1] + by) * sc);
                    }
            }
        } else {
            #pragma unroll
            for (int nsub = 0; nsub < 8; nsub++) {
                const int col = wn + nsub * 8 + tq * 2;
                const float bx = gate_b[col], by = gate_b[col + 1];
                #pragma unroll
                for (int msub = 0; msub < 2; msub++)
                    #pragma unroll
                    for (int rr = 0; rr < 2; rr++) {
                        const int row = wm + msub * 16 + quad + rr * 8;
                        const float g0 = 1.0f / (1.0f + __expf(-(acc[msub][nsub][2 * rr]     + bx)));
                        const float g1 = 1.0f / (1.0f + __expf(-(acc[msub][nsub][2 * rr + 1] + by)));
                        *reinterpret_cast<uint32_t*>(sC + row * SPITCH + col) = packbf(g0, g1);
                    }
            }
        }
        __syncthreads();   // MMA(nb) done everywhere; sC staged; sB reload safe

        // ---- prefetch next B tile (overlaps the C write-out below) ----
        if (nb < 3) {
            const __nv_bfloat16* bsrc = g_wqkv_b16 + (size_t)((nb + 1) * 128 + br) * 128 + bh * 64;
            #pragma unroll
            for (int i = 0; i < 8; i++) cp16(bdst + i * 16, bsrc + i * 8);
            CP_COMMIT();
        }

        // ---- coalesced global write from sC ----
        if (nb < 3) {
            #pragma unroll
            for (int it = 0; it < 16; it++) {
                const int c = it * 256 + tid;        // 0..4095 uint2 chunks
                const int seg = c >> 3, u = c & 7;   // 512 segments of 64B
                const int rr = seg >> 2, hh = seg & 3;
                const uint2 v = *reinterpret_cast<const uint2*>(
                    reinterpret_cast<const char*>(sC) + rr * (SPITCH * 2) + hh * 64 + u * 8);
                const size_t dst = (((size_t)nb * NT + rn0 + rr) * NH + hh) * ((size_t)NT * HD)
                                   + (size_t)ri0 * HD + u * 4;
                *reinterpret_cast<uint2*>(g_qkv_b16 + dst) = v;
            }
            CP_WAIT0();
            __syncthreads();   // B(nb+1) visible; sC free
        } else {
            #pragma unroll
            for (int it = 0; it < 8; it++) {
                const int c = it * 256 + tid;
                const int row = c >> 4, u = c & 15;
                const uint4 v = *reinterpret_cast<const uint4*>(
                    reinterpret_cast<const char*>(sC) + row * (SPITCH * 2) + u * 16);
                reinterpret_cast<uint4*>(g_gate_b16 + (size_t)(m0 + row) * 128)[u] = v;
            }
        }
    }
}

// ---------------------------------------------------------------------------
// Kernel 2: tensor-core attention, register-resident softmax, NO max pass,
//   single-barrier column reduce (each thread sums its own columns' partials).
//   grid (384, 4), 256 threads (8 warps x 48 rows), 2 CTAs/SM. 1 barrier/tile.
// ---------------------------------------------------------------------------
#define AQP 40      // Q/K pitch (bf16 elems)
#define AVP 392     // Vt pitch (bf16 elems)
#define AOFF_Q   0
#define AOFF_K   30720
#define AOFF_VT  61440
#define AOFF_RED 86528
#define ATTN_SMEM 87808

__global__ __launch_bounds__(256, 2) void k_attn_mma() {
    const int n = blockIdx.x, h = blockIdx.y;
    extern __shared__ __align__(16) char dyn[];
    __nv_bfloat16* sQ  = reinterpret_cast<__nv_bfloat16*>(dyn + AOFF_Q);
    __nv_bfloat16* sK  = reinterpret_cast<__nv_bfloat16*>(dyn + AOFF_K);
    __nv_bfloat16* sVt = reinterpret_cast<__nv_bfloat16*>(dyn + AOFF_VT);
    float* sRed = reinterpret_cast<float*>(dyn + AOFF_RED);   // [col][warp] 32x8

    const int tid = threadIdx.x, lane = tid & 31, wid = tid >> 5;
    const int wm = wid * 48;
    const int quad = lane >> 2, tq = lane & 3;

    const uint32_t sQ_u  = smem_to_u32(sQ);
    const uint32_t sK_u  = smem_to_u32(sK);
    const uint32_t sVt_u = smem_to_u32(sVt);

    // ---- load Q, K via cp.async; V through registers (transposed store) ----
    const size_t tstride = (size_t)NT * NH * NT * HD;
    const size_t base    = ((size_t)n * NH + h) * ((size_t)NT * HD);
    const __nv_bfloat16* gQ = g_qkv_b16 + base;
    const __nv_bfloat16* gK = g_qkv_b16 + tstride + base;
    const uint4* gV = reinterpret_cast<const uint4*>(g_qkv_b16 + 2 * tstride + base);
    for (int c = tid; c < NT * HD / 8; c += 256) {
        const int row = c >> 2;
        const int c8  = (c & 3) << 3;
        cp16(sQ_u + (uint32_t)((row * AQP + c8) * 2), gQ + row * HD + c8);
        cp16(sK_u + (uint32_t)((row * AQP + c8) * 2), gK + row * HD + c8);
        uint4 v = gV[c];
        __nv_bfloat16 tmp[8];
        *reinterpret_cast<uint4*>(tmp) = v;
        #pragma unroll
        for (int d = 0; d < 8; d++) sVt[(c8 + d) * AVP + row] = tmp[d];
    }
    CP_COMMIT();
    CP_WAIT0();
    __syncthreads();

    const uint32_t aQbase = sQ_u + (uint32_t)(((wm + (lane & 15)) * AQP + ((lane >> 4) << 3)) * 2);
    const uint32_t bRow = (uint32_t)((lane & 7) + ((lane >> 4) << 3));
    const uint32_t bCol = (uint32_t)(((lane >> 3) & 1) << 3);

    float oacc[3][4][4];
    #pragma unroll
    for (int mf = 0; mf < 3; mf++)
        #pragma unroll
        for (int nf = 0; nf < 4; nf++)
            #pragma unroll
            for (int q = 0; q < 4; q++) oacc[mf][nf][q] = 0.0f;

    for (int t = 0; t < 12; t++) {
        const int j0 = t * 32;

        // ---- S = Q K^T ----
        float sacc[3][4][4];
        #pragma unroll
        for (int mf = 0; mf < 3; mf++)
            #pragma unroll
            for (int nf = 0; nf < 4; nf++)
                #pragma unroll
                for (int q = 0; q < 4; q++) sacc[mf][nf][q] = 0.0f;

        #pragma unroll
        for (int kk = 0; kk < 2; kk++) {
            uint32_t a[3][4];
            #pragma unroll
            for (int mf = 0; mf < 3; mf++)
                ldsm4(a[mf], aQbase + (uint32_t)((mf * 16 * AQP + kk * 16) * 2));
            #pragma unroll
            for (int nf16 = 0; nf16 < 2; nf16++) {
                uint32_t b[4];
                ldsm4(b, sK_u + (uint32_t)(((j0 + nf16 * 16 + bRow) * AQP + bCol + kk * 16) * 2));
                #pragma unroll
                for (int mf = 0; mf < 3; mf++) {
                    mma_bf16(sacc[mf][2 * nf16],     a[mf], b);
                    mma_bf16(sacc[mf][2 * nf16 + 1], a[mf], b + 2);
                }
            }
        }

        // ---- exp2 (no max: LN-bounded scores) + per-warp column partials ----
        float ps[8];
        #pragma unroll
        for (int k = 0; k < 8; k++) ps[k] = 0.0f;
        #pragma unroll
        for (int mf = 0; mf < 3; mf++)
            #pragma unroll
            for (int nf = 0; nf < 4; nf++)
                #pragma unroll
                for (int q = 0; q < 4; q++) {
                    const float e = ex2(sacc[mf][nf][q]);
                    sacc[mf][nf][q] = e;
                    ps[2 * nf + (q & 1)] += e;
                }
        #pragma unroll
        for (int off = 4; off < 32; off <<= 1)
            #pragma unroll
            for (int k = 0; k < 8; k++)
                ps[k] += __shfl_xor_sync(0xffffffffu, ps[k], off);
        if (lane < 4) {
            #pragma unroll
            for (int nf = 0; nf < 4; nf++)
                #pragma unroll
                for (int bb = 0; bb < 2; bb++)
                    sRed[(nf * 8 + tq * 2 + bb) * 8 + wid] = ps[2 * nf + bb];
        }
        __syncthreads();                                  // single barrier

        // ---- every thread sums its own 8 columns' 8-warp partials ----
        float inv[8];
        #pragma unroll
        for (int nf = 0; nf < 4; nf++)
            #pragma unroll
            for (int bb = 0; bb < 2; bb++) {
                const float4* pr = reinterpret_cast<const float4*>(
                    &sRed[(nf * 8 + tq * 2 + bb) * 8]);
                const float4 p0 = pr[0], p1 = pr[1];
                const float s = ((p0.x + p0.y) + (p0.z + p0.w))
                              + ((p1.x + p1.y) + (p1.z + p1.w));
                inv[2 * nf + bb] = __fdividef(1.0f, s);
            }
        #pragma unroll
        for (int mf = 0; mf < 3; mf++)
            #pragma unroll
            for (int nf = 0; nf < 4; nf++)
                #pragma unroll
                for (int q = 0; q < 4; q++)
                    sacc[mf][nf][q] *= inv[2 * nf + (q & 1)];

        // ---- O += P V ----
        #pragma unroll
        for (int kk = 0; kk < 2; kk++) {
            uint32_t a[3][4];
            #pragma unroll
            for (int mf = 0; mf < 3; mf++) {
                a[mf][0] = packbf(sacc[mf][2 * kk][0],     sacc[mf][2 * kk][1]);
                a[mf][1] = packbf(sacc[mf][2 * kk][2],     sacc[mf][2 * kk][3]);
                a[mf][2] = packbf(sacc[mf][2 * kk + 1][0], sacc[mf][2 * kk + 1][1]);
                a[mf][3] = packbf(sacc[mf][2 * kk + 1][2], sacc[mf][2 * kk + 1][3]);
            }
            #pragma unroll
            for (int nf16 = 0; nf16 < 2; nf16++) {
                uint32_t b[4];
                ldsm4(b, sVt_u + (uint32_t)(((nf16 * 16 + bRow) * AVP + j0 + bCol + kk * 16) * 2));
                #pragma unroll
                for (int mf = 0; mf < 3; mf++) {
                    mma_bf16(oacc[mf][2 * nf16],     a[mf], b);
                    mma_bf16(oacc[mf][2 * nf16 + 1], a[mf], b + 2);
                }
            }
        }
        // sRed rewritten next tile only after that tile's shfl phase; the
        // pre-write __syncthreads of the next tile is not needed because the
        // next write to sRed[(col)*8+wid] comes from the same warp (wid) that
        // read it is... NOT guaranteed across warps -> keep order: writes to
        // sRed happen after all warps' reads of this tile. Enforce:
        __syncthreads();                                  // protects sRed reuse
    }

    // ---- stage O (reuse sQ region), then coalesced global write ----
    #pragma unroll
    for (int mf = 0; mf < 3; mf++)
        #pragma unroll
        for (int nf = 0; nf < 4; nf++)
            #pragma unroll
            for (int rr = 0; rr < 2; rr++) {
                const int row = wm + mf * 16 + quad + rr * 8;
                const int col = nf * 8 + tq * 2;
                *reinterpret_cast<uint32_t*>(sQ + row * AQP + col) =
                    packbf(oacc[mf][nf][2 * rr], oacc[mf][nf][2 * rr + 1]);
            }
    __syncthreads();
    for (int c = tid; c < NT * 16; c += 256) {
        const int row = c >> 4, u = c & 15;
        const uint32_t v = *reinterpret_cast<const uint32_t*>(
            reinterpret_cast<const char*>(sQ) + row * (AQP * 2) + u * 4);
        *reinterpret_cast<uint32_t*>(
            g_ao_b16 + ((size_t)row * NT + n) * CZ + h * HD + u * 2) = v;
    }
}

// ---------------------------------------------------------------------------
// Kernel 3: GEMM  tmp = ao @ out_w + out_b ; out = z + gate * tmp
//   128x128 tiles, 256 threads, 2 CTAs/SM, direct quad epilogue (R11 config).
// ---------------------------------------------------------------------------
__global__ __launch_bounds__(256, 2) void k_gemm_out_mma(const float* __restrict__ out_b,
                                                         const float* __restrict__ z,
                                                         float* __restrict__ out) {
    extern __shared__ __align__(16) char dyn[];
    __nv_bfloat16* sA = reinterpret_cast<__nv_bfloat16*>(dyn);
    __nv_bfloat16* sB = sA + 128 * SPITCH;
    const int tid = threadIdx.x;
    const int m0  = blockIdx.x * 128;

    const uint32_t sA_u = smem_to_u32(sA);
    const uint32_t sB_u = smem_to_u32(sB);

    {
        const int r = tid >> 1;
        const int c = (tid & 1) * 64;
        const __nv_bfloat16* ga = g_ao_b16 + (size_t)(m0 + r) * 128 + c;
        const __nv_bfloat16* gb = g_wout_b16 + (size_t)r * 128 + c;
        const uint32_t da = sA_u + (uint32_t)((r * SPITCH + c) * 2);
        const uint32_t db = sB_u + (uint32_t)((r * SPITCH + c) * 2);
        #pragma unroll
        for (int i = 0; i < 8; i++) { cp16(da + i * 16, ga + i * 8); cp16(db + i * 16, gb + i * 8); }
    }
    CP_COMMIT();
    CP_WAIT0();
    __syncthreads();

    const int lane = tid & 31, wid = tid >> 5;
    const int wm = (wid & 3) * 32;
    const int wn = (wid >> 2) * 64;

    const uint32_t aaddr0 = sA_u + (uint32_t)(((wm + (lane & 15)) * SPITCH + ((lane >> 4) << 3)) * 2);
    const uint32_t aaddr1 = aaddr0 + 16 * SPITCH * 2;
    const uint32_t baddr  = sB_u + (uint32_t)(((wn + (lane & 7) + ((lane >> 4) << 3)) * SPITCH
                                               + (((lane >> 3) & 1) << 3)) * 2);

    float acc[2][8][4];
    #pragma unroll
    for (int m = 0; m < 2; m++)
        #pragma unroll
        for (int n = 0; n < 8; n++)
            #pragma unroll
            for (int q = 0; q < 4; q++) acc[m][n][q] = 0.0f;

    #pragma unroll
    for (int k0 = 0; k0 < 128; k0 += 16) {
        uint32_t a0[4], a1[4];
        ldsm4(a0, aaddr0 + k0 * 2);
        ldsm4(a1, aaddr1 + k0 * 2);
        #pragma unroll
        for (int np = 0; np < 4; np++) {
            uint32_t b[4];
            ldsm4(b, baddr + (uint32_t)(np * 16 * SPITCH * 2) + k0 * 2);
            mma_bf16(acc[0][2 * np],     a0, b);
            mma_bf16(acc[0][2 * np + 1], a0, b + 2);
            mma_bf16(acc[1][2 * np],     a1, b);
            mma_bf16(acc[1][2 * np + 1], a1, b + 2);
        }
    }

    // ---- direct epilogue: 32B-per-quad accesses (1 sector each, no waste) ----
    const int quad = lane >> 2, tq = lane & 3;
    #pragma unroll
    for (int nsub = 0; nsub < 8; nsub++) {
        const int col = wn + nsub * 8 + tq * 2;
        const float bx = out_b[col], by = out_b[col + 1];
        #pragma unroll
        for (int msub = 0; msub < 2; msub++) {
            #pragma unroll
            for (int rr = 0; rr < 2; rr++) {
                const int r = m0 + wm + msub * 16 + quad + rr * 8;
                const size_t idx = (size_t)r * 128 + col;
                const float2 zv = *reinterpret_cast<const float2*>(&z[idx]);
                const __nv_bfloat162 gb2 = *reinterpret_cast<const __nv_bfloat162*>(&g_gate_b16[idx]);
                const float2 gv = __bfloat1622float2(gb2);
                float2 o;
                o.x = fmaf(gv.x, acc[msub][nsub][2 * rr]     + bx, zv.x);
                o.y = fmaf(gv.y, acc[msub][nsub][2 * rr + 1] + by, zv.y);
                *reinterpret_cast<float2*>(&out[idx]) = o;
            }
        }
    }
}

// ---------------------------------------------------------------------------
extern "C" void kernel_launch(void* const* d_in, const int* in_sizes, int n_in,
                              void* d_out, int out_size) {
    const float* z      = (const float*)d_in[0];
    const float* ln_w   = (const float*)d_in[1];
    const float* ln_b   = (const float*)d_in[2];
    const float* qkv_w  = (const float*)d_in[3];
    const float* qkv_b  = (const float*)d_in[4];
    const float* out_w  = (const float*)d_in[5];
    const float* out_b  = (const float*)d_in[6];
    const float* gate_w = (const float*)d_in[7];
    const float* gate_b = (const float*)d_in[8];
    float* out = (float*)d_out;

    const int g1_smem = 3 * 128 * SPITCH * (int)sizeof(__nv_bfloat16);   // 104448 B
    const int g3_smem = 2 * 128 * SPITCH * (int)sizeof(__nv_bfloat16);   // 69632 B
    cudaFuncSetAttribute(k_gemm_ln_qkvg, cudaFuncAttributeMaxDynamicSharedMemorySize, g1_smem);
    cudaFuncSetAttribute(k_gemm_out_mma, cudaFuncAttributeMaxDynamicSharedMemorySize, g3_smem);
    cudaFuncSetAttribute(k_attn_mma, cudaFuncAttributeMaxDynamicSharedMemorySize, ATTN_SMEM);

    k_convw<<<320, 256>>>(qkv_w, gate_w, out_w);
    k_gemm_ln_qkvg<<<NROWS / 128, 256, g1_smem>>>(z, ln_w, ln_b, qkv_b, gate_b);
    k_attn_mma<<<dim3(NT, NH), 256, ATTN_SMEM>>>();
    k_gemm_out_mma<<<NROWS / 128, 256, g3_smem>>>(out_b, z, out);
}

// round 14
// speedup vs baseline: 1.1652x; 1.1652x over previous
#include <cuda_runtime.h>
#include <cuda_bf16.h>
#include <math.h>
#include <cstdint>

#define NT 384
#define CZ 128
#define NH 4
#define HD 32
#define NROWS (NT*NT)   // 147456

// q pre-scale: (1/sqrt(32)) * log2(e)  -> attention uses exp2
#define QSC 0.25503540392906837f

// ---------------- scratch (device globals) ----------------
__device__ __nv_bfloat16  g_qkv_b16[(size_t)3 * NT * NH * NT * HD]; // [t][n][h][i][d]
__device__ __nv_bfloat16  g_gate_b16[(size_t)NROWS * CZ];           // sigmoid(gate), bf16
__device__ __nv_bfloat16  g_ao_b16[(size_t)NROWS * CZ];             // attention out, bf16
__device__ __nv_bfloat16  g_wqkv_b16[512 * 128];                    // [n][k]  (qkv | gate)
__device__ __nv_bfloat16  g_wout_b16[128 * 128];                    // [n][k]

// ---------------- helpers ----------------
__device__ __forceinline__ uint32_t smem_to_u32(const void* p) {
    uint32_t a;
    asm("{ .reg .u64 t; cvta.to.shared.u64 t, %1; cvt.u32.u64 %0, t; }" : "=r"(a) : "l"(p));
    return a;
}
__device__ __forceinline__ void ldsm4(uint32_t* r, uint32_t a) {
    asm volatile("ldmatrix.sync.aligned.m8n8.x4.shared.b16 {%0,%1,%2,%3}, [%4];"
        : "=r"(r[0]), "=r"(r[1]), "=r"(r[2]), "=r"(r[3]) : "r"(a));
}
__device__ __forceinline__ void mma_bf16(float* d, const uint32_t* a, const uint32_t* b) {
    asm volatile("mma.sync.aligned.m16n8k16.row.col.f32.bf16.bf16.f32 "
        "{%0,%1,%2,%3}, {%4,%5,%6,%7}, {%8,%9}, {%0,%1,%2,%3};"
        : "+f"(d[0]), "+f"(d[1]), "+f"(d[2]), "+f"(d[3])
        : "r"(a[0]), "r"(a[1]), "r"(a[2]), "r"(a[3]), "r"(b[0]), "r"(b[1]));
}
__device__ __forceinline__ uint32_t packbf(float lo, float hi) {
    __nv_bfloat162 p = __floats2bfloat162_rn(lo, hi);
    return *reinterpret_cast<uint32_t*>(&p);
}
__device__ __forceinline__ void cp16(uint32_t s, const void* g) {
    asm volatile("cp.async.cg.shared.global [%0], [%1], 16;" :: "r"(s), "l"(g));
}
#define CP_COMMIT() asm volatile("cp.async.commit_group;")
#define CP_WAIT0()  asm volatile("cp.async.wait_group 0;")
__device__ __forceinline__ float ex2(float x) {
    float y; asm("ex2.approx.ftz.f32 %0, %1;" : "=f"(y) : "f"(x)); return y;
}

// ---------------------------------------------------------------------------
// Kernel 0: convert weights to bf16, transposed to [n][k]
// ---------------------------------------------------------------------------
__global__ __launch_bounds__(256) void k_convw(const float* __restrict__ qkv_w,
                                               const float* __restrict__ gate_w,
                                               const float* __restrict__ out_w) {
    const int idx = blockIdx.x * 256 + threadIdx.x;
    if (idx < 512 * 128) {
        const int n = idx >> 7, k = idx & 127;
        const float v = (n < 384) ? qkv_w[k * 384 + n] : gate_w[k * 128 + (n - 384)];
        g_wqkv_b16[idx] = __float2bfloat16_rn(v);
    } else {
        const int j = idx - 512 * 128;   // < 16384
        const int n = j >> 7, k = j & 127;
        g_wout_b16[j] = __float2bfloat16_rn(out_w[k * 128 + n]);
    }
}

// ---------------------------------------------------------------------------
// Kernel 1: fused LN + GEMM [128 rows] x [128 -> 512 cols], pipelined, 2 CTAs/SM.
// ---------------------------------------------------------------------------
#define SPITCH 136   // bf16 elements per smem row

__global__ __launch_bounds__(256, 2) void k_gemm_ln_qkvg(const float* __restrict__ z,
                                                         const float* __restrict__ lnw,
                                                         const float* __restrict__ lnb,
                                                         const float* __restrict__ qkv_b,
                                                         const float* __restrict__ gate_b) {
    extern __shared__ __align__(16) char dyn[];
    __nv_bfloat16* sA = reinterpret_cast<__nv_bfloat16*>(dyn);
    __nv_bfloat16* sB = sA + 128 * SPITCH;
    __nv_bfloat16* sC = sB + 128 * SPITCH;
    const int tid = threadIdx.x;
    const int m0  = blockIdx.x * 128;

    const uint32_t sB_u = smem_to_u32(sB);
    const int br  = tid >> 1;           // B-copy row
    const int bh  = tid & 1;            // half-row
    const uint32_t bdst = sB_u + (uint32_t)((br * SPITCH + bh * 64) * 2);
    const __nv_bfloat16* bsrc0 = g_wqkv_b16 + (size_t)br * 128 + bh * 64;

    // ---- prefetch B tile 0 ----
    #pragma unroll
    for (int i = 0; i < 8; i++) cp16(bdst + i * 16, bsrc0 + i * 8);
    CP_COMMIT();

    // ---- LayerNorm into sA (bf16): 4 threads/row, 2 passes (32 live floats) ----
    #pragma unroll
    for (int pass = 0; pass < 2; pass++) {
        const int r = pass * 64 + (tid >> 2);
        const int qt = tid & 3;                       // quarter-row (32 floats)
        const float4* zr = reinterpret_cast<const float4*>(
            z + (size_t)(m0 + r) * 128 + qt * 32);
        float x[32];
        #pragma unroll
        for (int p = 0; p < 8; p++) {
            float4 v = zr[p];
            x[4 * p] = v.x; x[4 * p + 1] = v.y; x[4 * p + 2] = v.z; x[4 * p + 3] = v.w;
        }
        float s = 0.f, ss = 0.f;
        #pragma unroll
        for (int c = 0; c < 32; c++) { s += x[c]; ss += x[c] * x[c]; }
        s  += __shfl_xor_sync(0xffffffffu, s, 1);
        ss += __shfl_xor_sync(0xffffffffu, ss, 1);
        s  += __shfl_xor_sync(0xffffffffu, s, 2);
        ss += __shfl_xor_sync(0xffffffffu, ss, 2);
        const float mu  = s * (1.0f / 128.0f);
        const float var = ss * (1.0f / 128.0f) - mu * mu;
        const float inv = rsqrtf(var + 1e-5f);
        const float4* w4 = reinterpret_cast<const float4*>(lnw + qt * 32);
        const float4* b4 = reinterpret_cast<const float4*>(lnb + qt * 32);
        uint32_t* dst = reinterpret_cast<uint32_t*>(sA + r * SPITCH + qt * 32);
        #pragma unroll
        for (int p = 0; p < 8; p++) {
            const float4 w = w4[p], b = b4[p];
            dst[2 * p]     = packbf((x[4 * p]     - mu) * inv * w.x + b.x,
                                    (x[4 * p + 1] - mu) * inv * w.y + b.y);
            dst[2 * p + 1] = packbf((x[4 * p + 2] - mu) * inv * w.z + b.z,
                                    (x[4 * p + 3] - mu) * inv * w.w + b.w);
        }
    }
    CP_WAIT0();
    __syncthreads();

    const int lane = tid & 31, wid = tid >> 5;
    const int wm = (wid & 3) * 32;
    const int wn = (wid >> 2) * 64;
    const int quad = lane >> 2, tq = lane & 3;

    const uint32_t sA_u = smem_to_u32(sA);
    const uint32_t aaddr0 = sA_u + (uint32_t)(((wm + (lane & 15)) * SPITCH + ((lane >> 4) << 3)) * 2);
    const uint32_t aaddr1 = aaddr0 + 16 * SPITCH * 2;
    const uint32_t baddr  = sB_u + (uint32_t)(((wn + (lane & 7) + ((lane >> 4) << 3)) * SPITCH
                                               + (((lane >> 3) & 1) << 3)) * 2);

    const int rn0 = (blockIdx.x % 3) * 128;
    const int ri0 = blockIdx.x / 3;

    for (int nb = 0; nb < 4; nb++) {
        float acc[2][8][4];
        #pragma unroll
        for (int m = 0; m < 2; m++)
            #pragma unroll
            for (int n = 0; n < 8; n++)
                #pragma unroll
                for (int q = 0; q < 4; q++) acc[m][n][q] = 0.0f;

        #pragma unroll
        for (int k0 = 0; k0 < 128; k0 += 16) {
            uint32_t a0[4], a1[4];
            ldsm4(a0, aaddr0 + k0 * 2);
            ldsm4(a1, aaddr1 + k0 * 2);
            #pragma unroll
            for (int np = 0; np < 4; np++) {
                uint32_t b[4];
                ldsm4(b, baddr + (uint32_t)(np * 16 * SPITCH * 2) + k0 * 2);
                mma_bf16(acc[0][2 * np],     a0, b);
                mma_bf16(acc[0][2 * np + 1], a0, b + 2);
                mma_bf16(acc[1][2 * np],     a1, b);
                mma_bf16(acc[1][2 * np + 1], a1, b + 2);
            }
        }

        // ---- stage C tile into sC (bias / activation applied) ----
        if (nb < 3) {
            const float sc = (nb == 0) ? QSC : 1.0f;
            #pragma unroll
            for (int nsub = 0; nsub < 8; nsub++) {
                const int col = wn + nsub * 8 + tq * 2;
                const float bx = qkv_b[nb * 128 + col], by = qkv_b[nb * 128 + col + 1];
                #pragma unroll
                for (int msub = 0; msub < 2; msub++)
                    #pragma unroll
                    for (int rr = 0; rr < 2; rr++) {
                        const int row = wm + msub * 16 + quad + rr * 8;
                        *reinterpret_cast<uint32_t*>(sC + row * SPITCH + col) =
                            packbf((acc[msub][nsub][2 * rr]     + bx) * sc,
                                   (acc[msub][nsub][2 * rr + 1] + by) * sc);
                    }
            }
        } else {
            #pragma unroll
            for (int nsub = 0; nsub < 8; nsub++) {
                const int col = wn + nsub * 8 + tq * 2;
                const float bx = gate_b[col], by = gate_b[col + 1];
                #pragma unroll
                for (int msub = 0; msub < 2; msub++)
                    #pragma unroll
                    for (int rr = 0; rr < 2; rr++) {
                        const int row = wm + msub * 16 + quad + rr * 8;
                        const float g0 = 1.0f / (1.0f + __expf(-(acc[msub][nsub][2 * rr]     + bx)));
                        const float g1 = 1.0f / (1.0f + __expf(-(acc[msub][nsub][2 * rr + 1] + by)));
                        *reinterpret_cast<uint32_t*>(sC + row * SPITCH + col) = packbf(g0, g1);
                    }
            }
        }
        __syncthreads();   // MMA(nb) done everywhere; sC staged; sB reload safe

        // ---- prefetch next B tile (overlaps the C write-out below) ----
        if (nb < 3) {
            const __nv_bfloat16* bsrc = g_wqkv_b16 + (size_t)((nb + 1) * 128 + br) * 128 + bh * 64;
            #pragma unroll
            for (int i = 0; i < 8; i++) cp16(bdst + i * 16, bsrc + i * 8);
            CP_COMMIT();
        }

        // ---- coalesced global write from sC ----
        if (nb < 3) {
            #pragma unroll
            for (int it = 0; it < 16; it++) {
                const int c = it * 256 + tid;        // 0..4095 uint2 chunks
                const int seg = c >> 3, u = c & 7;   // 512 segments of 64B
                const int rr = seg >> 2, hh = seg & 3;
                const uint2 v = *reinterpret_cast<const uint2*>(
                    reinterpret_cast<const char*>(sC) + rr * (SPITCH * 2) + hh * 64 + u * 8);
                const size_t dst = (((size_t)nb * NT + rn0 + rr) * NH + hh) * ((size_t)NT * HD)
                                   + (size_t)ri0 * HD + u * 4;
                *reinterpret_cast<uint2*>(g_qkv_b16 + dst) = v;
            }
            CP_WAIT0();
            __syncthreads();   // B(nb+1) visible; sC free
        } else {
            #pragma unroll
            for (int it = 0; it < 8; it++) {
                const int c = it * 256 + tid;
                const int row = c >> 4, u = c & 15;
                const uint4 v = *reinterpret_cast<const uint4*>(
                    reinterpret_cast<const char*>(sC) + row * (SPITCH * 2) + u * 16);
                reinterpret_cast<uint4*>(g_gate_b16 + (size_t)(m0 + row) * 128)[u] = v;
            }
        }
    }
}

// ---------------------------------------------------------------------------
// Kernel 2: tensor-core attention, register-resident softmax, NO max pass.
//   grid (384, 4), 256 threads (8 warps x 48 rows), 2 CTAs/SM. 2 barriers/tile.
// ---------------------------------------------------------------------------
#define AQP 40      // Q/K pitch (bf16 elems)
#define AVP 392     // Vt pitch (bf16 elems)
#define AOFF_Q   0
#define AOFF_K   30720
#define AOFF_VT  61440
#define AOFF_RED 86528
#define AOFF_INV 87552
#define ATTN_SMEM 87808

__global__ __launch_bounds__(256, 2) void k_attn_mma() {
    const int n = blockIdx.x, h = blockIdx.y;
    extern __shared__ __align__(16) char dyn[];
    __nv_bfloat16* sQ  = reinterpret_cast<__nv_bfloat16*>(dyn + AOFF_Q);
    __nv_bfloat16* sK  = reinterpret_cast<__nv_bfloat16*>(dyn + AOFF_K);
    __nv_bfloat16* sVt = reinterpret_cast<__nv_bfloat16*>(dyn + AOFF_VT);
    float* sRed = reinterpret_cast<float*>(dyn + AOFF_RED);   // [col][warp] 32x8
    float* sInv = reinterpret_cast<float*>(dyn + AOFF_INV);   // [32]

    const int tid = threadIdx.x, lane = tid & 31, wid = tid >> 5;
    const int wm = wid * 48;
    const int quad = lane >> 2, tq = lane & 3;

    const uint32_t sQ_u  = smem_to_u32(sQ);
    const uint32_t sK_u  = smem_to_u32(sK);
    const uint32_t sVt_u = smem_to_u32(sVt);

    // ---- load Q, K via cp.async; V through registers (transposed store) ----
    const size_t tstride = (size_t)NT * NH * NT * HD;
    const size_t base    = ((size_t)n * NH + h) * ((size_t)NT * HD);
    const __nv_bfloat16* gQ = g_qkv_b16 + base;
    const __nv_bfloat16* gK = g_qkv_b16 + tstride + base;
    const uint4* gV = reinterpret_cast<const uint4*>(g_qkv_b16 + 2 * tstride + base);
    for (int c = tid; c < NT * HD / 8; c += 256) {
        const int row = c >> 2;
        const int c8  = (c & 3) << 3;
        cp16(sQ_u + (uint32_t)((row * AQP + c8) * 2), gQ + row * HD + c8);
        cp16(sK_u + (uint32_t)((row * AQP + c8) * 2), gK + row * HD + c8);
        uint4 v = gV[c];
        __nv_bfloat16 tmp[8];
        *reinterpret_cast<uint4*>(tmp) = v;
        #pragma unroll
        for (int d = 0; d < 8; d++) sVt[(c8 + d) * AVP + row] = tmp[d];
    }
    CP_COMMIT();
    CP_WAIT0();
    __syncthreads();

    const uint32_t aQbase = sQ_u + (uint32_t)(((wm + (lane & 15)) * AQP + ((lane >> 4) << 3)) * 2);
    const uint32_t bRow = (uint32_t)((lane & 7) + ((lane >> 4) << 3));
    const uint32_t bCol = (uint32_t)(((lane >> 3) & 1) << 3);

    float oacc[3][4][4];
    #pragma unroll
    for (int mf = 0; mf < 3; mf++)
        #pragma unroll
        for (int nf = 0; nf < 4; nf++)
            #pragma unroll
            for (int q = 0; q < 4; q++) oacc[mf][nf][q] = 0.0f;

    for (int t = 0; t < 12; t++) {
        const int j0 = t * 32;

        // ---- S = Q K^T ----
        float sacc[3][4][4];
        #pragma unroll
        for (int mf = 0; mf < 3; mf++)
            #pragma unroll
            for (int nf = 0; nf < 4; nf++)
                #pragma unroll
                for (int q = 0; q < 4; q++) sacc[mf][nf][q] = 0.0f;

        #pragma unroll
        for (int kk = 0; kk < 2; kk++) {
            uint32_t a[3][4];
            #pragma unroll
            for (int mf = 0; mf < 3; mf++)
                ldsm4(a[mf], aQbase + (uint32_t)((mf * 16 * AQP + kk * 16) * 2));
            #pragma unroll
            for (int nf16 = 0; nf16 < 2; nf16++) {
                uint32_t b[4];
                ldsm4(b, sK_u + (uint32_t)(((j0 + nf16 * 16 + bRow) * AQP + bCol + kk * 16) * 2));
                #pragma unroll
                for (int mf = 0; mf < 3; mf++) {
                    mma_bf16(sacc[mf][2 * nf16],     a[mf], b);
                    mma_bf16(sacc[mf][2 * nf16 + 1], a[mf], b + 2);
                }
            }
        }

        // ---- exp2 (no max: LN-bounded scores) + column sum ----
        float ps[8];
        #pragma unroll
        for (int k = 0; k < 8; k++) ps[k] = 0.0f;
        #pragma unroll
        for (int mf = 0; mf < 3; mf++)
            #pragma unroll
            for (int nf = 0; nf < 4; nf++)
                #pragma unroll
                for (int q = 0; q < 4; q++) {
                    const float e = ex2(sacc[mf][nf][q]);
                    sacc[mf][nf][q] = e;
                    ps[2 * nf + (q & 1)] += e;
                }
        #pragma unroll
        for (int off = 4; off < 32; off <<= 1)
            #pragma unroll
            for (int k = 0; k < 8; k++)
                ps[k] += __shfl_xor_sync(0xffffffffu, ps[k], off);
        if (lane < 4) {
            #pragma unroll
            for (int nf = 0; nf < 4; nf++)
                #pragma unroll
                for (int bb = 0; bb < 2; bb++)
                    sRed[(nf * 8 + tq * 2 + bb) * 8 + wid] = ps[2 * nf + bb];
        }
        __syncthreads();                                  // bar 1
        if (tid < 32) {
            float s = 0.0f;
            #pragma unroll
            for (int w = 0; w < 8; w++) s += sRed[tid * 8 + w];
            sInv[tid] = __fdividef(1.0f, s);
        }
        __syncthreads();                                  // bar 2

        float inv[8];
        #pragma unroll
        for (int nf = 0; nf < 4; nf++)
            #pragma unroll
            for (int bb = 0; bb < 2; bb++)
                inv[2 * nf + bb] = sInv[nf * 8 + tq * 2 + bb];
        #pragma unroll
        for (int mf = 0; mf < 3; mf++)
            #pragma unroll
            for (int nf = 0; nf < 4; nf++)
                #pragma unroll
                for (int q = 0; q < 4; q++)
                    sacc[mf][nf][q] *= inv[2 * nf + (q & 1)];

        // ---- O += P V ----
        #pragma unroll
        for (int kk = 0; kk < 2; kk++) {
            uint32_t a[3][4];
            #pragma unroll
            for (int mf = 0; mf < 3; mf++) {
                a[mf][0] = packbf(sacc[mf][2 * kk][0],     sacc[mf][2 * kk][1]);
                a[mf][1] = packbf(sacc[mf][2 * kk][2],     sacc[mf][2 * kk][3]);
                a[mf][2] = packbf(sacc[mf][2 * kk + 1][0], sacc[mf][2 * kk + 1][1]);
                a[mf][3] = packbf(sacc[mf][2 * kk + 1][2], sacc[mf][2 * kk + 1][3]);
            }
            #pragma unroll
            for (int nf16 = 0; nf16 < 2; nf16++) {
                uint32_t b[4];
                ldsm4(b, sVt_u + (uint32_t)(((nf16 * 16 + bRow) * AVP + j0 + bCol + kk * 16) * 2));
                #pragma unroll
                for (int mf = 0; mf < 3; mf++) {
                    mma_bf16(oacc[mf][2 * nf16],     a[mf], b);
                    mma_bf16(oacc[mf][2 * nf16 + 1], a[mf], b + 2);
                }
            }
        }
    }

    // ---- stage O (reuse sQ region), then coalesced global write ----
    #pragma unroll
    for (int mf = 0; mf < 3; mf++)
        #pragma unroll
        for (int nf = 0; nf < 4; nf++)
            #pragma unroll
            for (int rr = 0; rr < 2; rr++) {
                const int row = wm + mf * 16 + quad + rr * 8;
                const int col = nf * 8 + tq * 2;
                *reinterpret_cast<uint32_t*>(sQ + row * AQP + col) =
                    packbf(oacc[mf][nf][2 * rr], oacc[mf][nf][2 * rr + 1]);
            }
    __syncthreads();
    for (int c = tid; c < NT * 16; c += 256) {
        const int row = c >> 4, u = c & 15;
        const uint32_t v = *reinterpret_cast<const uint32_t*>(
            reinterpret_cast<const char*>(sQ) + row * (AQP * 2) + u * 4);
        *reinterpret_cast<uint32_t*>(
            g_ao_b16 + ((size_t)row * NT + n) * CZ + h * HD + u * 2) = v;
    }
}

// ---------------------------------------------------------------------------
// Kernel 3: GEMM  tmp = ao @ out_w + out_b ; out = z + gate * tmp
//   128x128 tiles, 256 threads, 2 CTAs/SM, direct quad epilogue.
// ---------------------------------------------------------------------------
__global__ __launch_bounds__(256, 2) void k_gemm_out_mma(const float* __restrict__ out_b,
                                                         const float* __restrict__ z,
                                                         float* __restrict__ out) {
    extern __shared__ __align__(16) char dyn[];
    __nv_bfloat16* sA = reinterpret_cast<__nv_bfloat16*>(dyn);
    __nv_bfloat16* sB = sA + 128 * SPITCH;
    const int tid = threadIdx.x;
    const int m0  = blockIdx.x * 128;

    const uint32_t sA_u = smem_to_u32(sA);
    const uint32_t sB_u = smem_to_u32(sB);

    {
        const int r = tid >> 1;
        const int c = (tid & 1) * 64;
        const __nv_bfloat16* ga = g_ao_b16 + (size_t)(m0 + r) * 128 + c;
        const __nv_bfloat16* gb = g_wout_b16 + (size_t)r * 128 + c;
        const uint32_t da = sA_u + (uint32_t)((r * SPITCH + c) * 2);
        const uint32_t db = sB_u + (uint32_t)((r * SPITCH + c) * 2);
        #pragma unroll
        for (int i = 0; i < 8; i++) { cp16(da + i * 16, ga + i * 8); cp16(db + i * 16, gb + i * 8); }
    }
    CP_COMMIT();
    CP_WAIT0();
    __syncthreads();

    const int lane = tid & 31, wid = tid >> 5;
    const int wm = (wid & 3) * 32;
    const int wn = (wid >> 2) * 64;

    const uint32_t aaddr0 = sA_u + (uint32_t)(((wm + (lane & 15)) * SPITCH + ((lane >> 4) << 3)) * 2);
    const uint32_t aaddr1 = aaddr0 + 16 * SPITCH * 2;
    const uint32_t baddr  = sB_u + (uint32_t)(((wn + (lane & 7) + ((lane >> 4) << 3)) * SPITCH
                                               + (((lane >> 3) & 1) << 3)) * 2);

    float acc[2][8][4];
    #pragma unroll
    for (int m = 0; m < 2; m++)
        #pragma unroll
        for (int n = 0; n < 8; n++)
            #pragma unroll
            for (int q = 0; q < 4; q++) acc[m][n][q] = 0.0f;

    #pragma unroll
    for (int k0 = 0; k0 < 128; k0 += 16) {
        uint32_t a0[4], a1[4];
        ldsm4(a0, aaddr0 + k0 * 2);
        ldsm4(a1, aaddr1 + k0 * 2);
        #pragma unroll
        for (int np = 0; np < 4; np++) {
            uint32_t b[4];
            ldsm4(b, baddr + (uint32_t)(np * 16 * SPITCH * 2) + k0 * 2);
            mma_bf16(acc[0][2 * np],     a0, b);
            mma_bf16(acc[0][2 * np + 1], a0, b + 2);
            mma_bf16(acc[1][2 * np],     a1, b);
            mma_bf16(acc[1][2 * np + 1], a1, b + 2);
        }
    }

    // ---- direct epilogue: 32B-per-quad accesses (1 sector each, no waste) ----
    const int quad = lane >> 2, tq = lane & 3;
    #pragma unroll
    for (int nsub = 0; nsub < 8; nsub++) {
        const int col = wn + nsub * 8 + tq * 2;
        const float bx = out_b[col], by = out_b[col + 1];
        #pragma unroll
        for (int msub = 0; msub < 2; msub++) {
            #pragma unroll
            for (int rr = 0; rr < 2; rr++) {
                const int r = m0 + wm + msub * 16 + quad + rr * 8;
                const size_t idx = (size_t)r * 128 + col;
                const float2 zv = *reinterpret_cast<const float2*>(&z[idx]);
                const __nv_bfloat162 gb2 = *reinterpret_cast<const __nv_bfloat162*>(&g_gate_b16[idx]);
                const float2 gv = __bfloat1622float2(gb2);
                float2 o;
                o.x = fmaf(gv.x, acc[msub][nsub][2 * rr]     + bx, zv.x);
                o.y = fmaf(gv.y, acc[msub][nsub][2 * rr + 1] + by, zv.y);
                *reinterpret_cast<float2*>(&out[idx]) = o;
            }
        }
    }
}

// ---------------------------------------------------------------------------
extern "C" void kernel_launch(void* const* d_in, const int* in_sizes, int n_in,
                              void* d_out, int out_size) {
    const float* z      = (const float*)d_in[0];
    const float* ln_w   = (const float*)d_in[1];
    const float* ln_b   = (const float*)d_in[2];
    const float* qkv_w  = (const float*)d_in[3];
    const float* qkv_b  = (const float*)d_in[4];
    const float* out_w  = (const float*)d_in[5];
    const float* out_b  = (const float*)d_in[6];
    const float* gate_w = (const float*)d_in[7];
    const float* gate_b = (const float*)d_in[8];
    float* out = (float*)d_out;

    const int g1_smem = 3 * 128 * SPITCH * (int)sizeof(__nv_bfloat16);   // 104448 B
    const int g3_smem = 2 * 128 * SPITCH * (int)sizeof(__nv_bfloat16);   // 69632 B
    cudaFuncSetAttribute(k_gemm_ln_qkvg, cudaFuncAttributeMaxDynamicSharedMemorySize, g1_smem);
    cudaFuncSetAttribute(k_gemm_out_mma, cudaFuncAttributeMaxDynamicSharedMemorySize, g3_smem);
    cudaFuncSetAttribute(k_attn_mma, cudaFuncAttributeMaxDynamicSharedMemorySize, ATTN_SMEM);

    k_convw<<<320, 256>>>(qkv_w, gate_w, out_w);
    k_gemm_ln_qkvg<<<NROWS / 128, 256, g1_smem>>>(z, ln_w, ln_b, qkv_b, gate_b);
    k_attn_mma<<<dim3(NT, NH), 256, ATTN_SMEM>>>();
    k_gemm_out_mma<<<NROWS / 128, 256, g3_smem>>>(out_b, z, out);
}